// round 11
// baseline (speedup 1.0000x reference)
#include <cuda_runtime.h>
#include <cuda_fp16.h>
#include <stdint.h>

// TriangleMultiplicativeUpdate — persistent-CTA fused kernel.
// mma.sync m16n8k16 fp16 (fp32 accum), single-pass fp16 weights.
// Round 10: 1 CTA/SM (512 thr), ALL SIX weights resident in smem in a
// swizzled-compact layout (32KB each), loaded once per CTA; grid-stride
// over 64-row tiles. Kills the 12288 cp.async STS per tile that dominated
// LSU issue. Warp tile 16x32 keeps 'a' and 'gate' in registers (no fp16
// spill => error term removed). 4 barriers/tile.

#define NT 512
#define ZSTR 272u             // zn row stride (bytes), conflict-free ldmatrix

#define OFF_ZN  0u            // zn/xn: 64 x 272 fp16
#define OFF_W0  17408u        // 6 weight slots, 32768B each, swizzled
#define WSLOT(i) (OFF_W0 + (uint32_t)(i) * 32768u)
#define OFF_SB  214016u       // 8 x 128 floats (biases, ln_out w/b)
#define OFF_MK  218112u       // 64 floats (mask)
#define OFF_RED 218368u       // 64 x 4 float2 (LN_out partials)
#define SMEM_BYTES 220416

// weights as fp16, SWIZZLED image: elem (n,c) at byte b^((b>>4)&0x70),
// b = n*256 + c*2.  0=w_ap 1=w_ag 2=w_bp 3=w_bg 4=w_g 5=w_z
__device__ __align__(16) __half g_w[6][128 * 128];

__device__ __forceinline__ uint32_t s2u(const void* p) {
    uint32_t a;
    asm("{ .reg .u64 t; cvta.to.shared.u64 t, %1; cvt.u32.u64 %0, t; }" : "=r"(a) : "l"(p));
    return a;
}

#define LDSM4(r, a) \
    asm volatile("ldmatrix.sync.aligned.m8n8.x4.shared.b16 {%0,%1,%2,%3}, [%4];" \
        : "=r"((r)[0]), "=r"((r)[1]), "=r"((r)[2]), "=r"((r)[3]) : "r"(a))

#define MMAOP(d, a, b0, b1) \
    asm volatile("mma.sync.aligned.m16n8k16.row.col.f32.f16.f16.f32 " \
        "{%0,%1,%2,%3}, {%4,%5,%6,%7}, {%8,%9}, {%0,%1,%2,%3};" \
        : "+f"((d)[0]), "+f"((d)[1]), "+f"((d)[2]), "+f"((d)[3]) \
        : "r"((a)[0]), "r"((a)[1]), "r"((a)[2]), "r"((a)[3]), "r"(b0), "r"(b1))

#define CPA16(dst, src) \
    asm volatile("cp.async.cg.shared.global [%0], [%1], 16;" :: "r"(dst), "l"(src))
#define CP_COMMIT() asm volatile("cp.async.commit_group;" ::: "memory")
#define CP_WAIT0()  asm volatile("cp.async.wait_group 0;" ::: "memory")

__device__ __forceinline__ float sigm(float x) { return 1.0f / (1.0f + __expf(-x)); }

// single pass: acc[16] += A(16x128) @ W^T (32 cols), swizzled weight slot.
// off_k = ((k*32 + l16) ^ xv); second n-group is +4096 bytes.
__device__ __forceinline__ void mm1(float* acc, uint32_t aaddr, uint32_t wb,
                                    uint32_t l16, uint32_t xv) {
#pragma unroll
    for (int k = 0; k < 8; k++) {
        uint32_t ko = (uint32_t)k * 32u;
        uint32_t off = (ko + l16) ^ xv;
        uint32_t A[4], B0[4], B1[4];
        LDSM4(A, aaddr + ko);
        LDSM4(B0, wb + off);
        LDSM4(B1, wb + off + 4096u);
        MMAOP(acc + 0,  A, B0[0], B0[1]); MMAOP(acc + 4,  A, B0[2], B0[3]);
        MMAOP(acc + 8,  A, B1[0], B1[1]); MMAOP(acc + 12, A, B1[2], B1[3]);
    }
}

// paired pass: accP += A@Wp^T, accG += A@Wg^T; A fragments loaded once.
__device__ __forceinline__ void mm_pair(float* accP, float* accG, uint32_t aaddr,
                                        uint32_t wpb, uint32_t wgb,
                                        uint32_t l16, uint32_t xv) {
#pragma unroll
    for (int k = 0; k < 8; k++) {
        uint32_t ko = (uint32_t)k * 32u;
        uint32_t off = (ko + l16) ^ xv;
        uint32_t A[4], P0[4], P1[4], G0[4], G1[4];
        LDSM4(A, aaddr + ko);
        LDSM4(P0, wpb + off); LDSM4(P1, wpb + off + 4096u);
        LDSM4(G0, wgb + off); LDSM4(G1, wgb + off + 4096u);
        MMAOP(accP + 0,  A, P0[0], P0[1]); MMAOP(accP + 4,  A, P0[2], P0[3]);
        MMAOP(accP + 8,  A, P1[0], P1[1]); MMAOP(accP + 12, A, P1[2], P1[3]);
        MMAOP(accG + 0,  A, G0[0], G0[1]); MMAOP(accG + 4,  A, G0[2], G0[3]);
        MMAOP(accG + 8,  A, G1[0], G1[1]); MMAOP(accG + 12, A, G1[2], G1[3]);
    }
}

__global__ void kPrep(const float* __restrict__ w0, const float* __restrict__ w1,
                      const float* __restrict__ w2, const float* __restrict__ w3,
                      const float* __restrict__ w4, const float* __restrict__ w5) {
    const float* w;
    switch (blockIdx.x) {
        case 0: w = w0; break; case 1: w = w1; break; case 2: w = w2; break;
        case 3: w = w3; break; case 4: w = w4; break; default: w = w5; break;
    }
    char* img = (char*)g_w[blockIdx.x];
    for (int i = threadIdx.x; i < 128 * 128; i += blockDim.x) {
        int n = i >> 7, c = i & 127;
        uint32_t b = (uint32_t)n * 256u + (uint32_t)c * 2u;
        uint32_t sw = b ^ ((b >> 4) & 0x70u);
        *(__half*)(img + sw) = __float2half(__ldg(w + i));
    }
}

__global__ void __launch_bounds__(NT, 1)
tmu_kernel(const float* __restrict__ z, const float* __restrict__ mask,
           const float* __restrict__ b_ap, const float* __restrict__ b_ag,
           const float* __restrict__ b_bp, const float* __restrict__ b_bg,
           const float* __restrict__ b_g,  const float* __restrict__ b_z,
           const float* __restrict__ ln_in_w,  const float* __restrict__ ln_in_b,
           const float* __restrict__ ln_out_w, const float* __restrict__ ln_out_b,
           float* __restrict__ out, int ntiles) {
    extern __shared__ char sm[];
    const uint32_t smb = s2u(sm);
    const int t = threadIdx.x;
    const int w = t >> 5, lid = t & 31;
    const int quad = lid >> 2, qt = lid & 3;
    const int wr = (w & 3) * 16;          // 4 row-warps x 16 rows
    const int wc = (w >> 2) * 32;         // 4 col-warps x 32 cols
    const int wcid = w >> 2;
    const int r0 = wr + quad, r1 = r0 + 8;

    float* bias = (float*)(sm + OFF_SB);
    float* mk   = (float*)(sm + OFF_MK);
    float2* red = (float2*)(sm + OFF_RED);

    // ---- load ALL SIX weights once (swizzled images copied linearly) ----
#pragma unroll
    for (int m = 0; m < 6; m++) {
        const char* s = (const char*)g_w[m];
#pragma unroll
        for (int i = 0; i < 4; i++) {
            int cid = t + i * NT;          // 2048 16B chunks per matrix
            CPA16(smb + WSLOT(m) + (uint32_t)cid * 16u, s + (size_t)cid * 16);
        }
    }
    CP_COMMIT();

    if (t < 128) {
        bias[t] = __ldg(b_ap + t);           bias[128 + t] = __ldg(b_ag + t);
        bias[256 + t] = __ldg(b_bp + t);     bias[384 + t] = __ldg(b_bg + t);
        bias[512 + t] = __ldg(b_g + t);      bias[640 + t] = __ldg(b_z + t);
        bias[768 + t] = __ldg(ln_out_w + t); bias[896 + t] = __ldg(ln_out_b + t);
    }

    // per-warp ldmatrix constants
    const uint32_t aaddr0 = smb + OFF_ZN +
        (uint32_t)(wr + (lid & 15)) * ZSTR + (uint32_t)(lid >> 4) * 16u;
    const int n_lane = wc + (lid & 7) + ((lid >> 4) << 3);
    const uint32_t l16 = (uint32_t)((lid >> 3) & 1) * 16u;
    const uint32_t xv = (uint32_t)(n_lane & 7) << 4;
    const uint32_t wnl = (uint32_t)n_lane * 256u;
    const uint32_t W0 = smb + WSLOT(0) + wnl, W1 = smb + WSLOT(1) + wnl;
    const uint32_t W2 = smb + WSLOT(2) + wnl, W3 = smb + WSLOT(3) + wnl;
    const uint32_t W4 = smb + WSLOT(4) + wnl, W5 = smb + WSLOT(5) + wnl;

    CP_WAIT0();   // weights landed (visibility via first __syncthreads)

    for (int tile = blockIdx.x; tile < ntiles; tile += gridDim.x) {
        const size_t row0 = (size_t)tile * 64;

        // ---- LN_in: 8 threads/row over 64 rows; write zn fp16 ----
        {
            const int r = t >> 3, q = t & 7;
            const float* zr = z + (row0 + r) * 128 + q * 16;
            float v[16], s = 0.f, s2 = 0.f;
#pragma unroll
            for (int i = 0; i < 4; i++) {
                float4 f = __ldg((const float4*)(zr + 4 * i));
                v[4*i] = f.x; v[4*i+1] = f.y; v[4*i+2] = f.z; v[4*i+3] = f.w;
                s += f.x + f.y + f.z + f.w;
                s2 += f.x*f.x + f.y*f.y + f.z*f.z + f.w*f.w;
            }
            s  += __shfl_xor_sync(~0u, s, 1);  s  += __shfl_xor_sync(~0u, s, 2);
            s  += __shfl_xor_sync(~0u, s, 4);
            s2 += __shfl_xor_sync(~0u, s2, 1); s2 += __shfl_xor_sync(~0u, s2, 2);
            s2 += __shfl_xor_sync(~0u, s2, 4);
            float mu = s * (1.f / 128);
            float rstd = rsqrtf(fmaxf(s2 * (1.f / 128) - mu * mu, 0.f) + 1e-5f);
#pragma unroll
            for (int j = 0; j < 2; j++) {
                union { uint4 u; __half b[8]; } H;
#pragma unroll
                for (int i = 0; i < 8; i++) {
                    int c = q * 16 + j * 8 + i;
                    float f = (v[j*8+i] - mu) * rstd * __ldg(ln_in_w + c) + __ldg(ln_in_b + c);
                    H.b[i] = __float2half(f);
                }
                *(uint4*)(sm + OFF_ZN + (uint32_t)r * ZSTR + (uint32_t)(q * 2 + j) * 16u) = H.u;
            }
            if (q == 0) mk[r] = __ldg(mask + row0 + r);
        }
        __syncthreads();                       // S1: zn + mk visible (+W on iter 0)

        float a[16], x[16], gate[16], accP[16], accG[16];
        const float m0 = mk[r0], m1 = mk[r1];

        // ===== pass P01: accP = zn@w_ap^T, accG = zn@w_ag^T; a in regs =====
#pragma unroll
        for (int e = 0; e < 16; e++) { accP[e] = 0.f; accG[e] = 0.f; }
        mm_pair(accP, accG, aaddr0, W0, W1, l16, xv);
#pragma unroll
        for (int nb = 0; nb < 4; nb++) {
            int e = nb * 4, col = wc + nb * 8 + qt * 2;
            a[e]   = (accP[e]   + bias[col])   * sigm(accG[e]   + bias[128 + col])   * m0;
            a[e+1] = (accP[e+1] + bias[col+1]) * sigm(accG[e+1] + bias[128 + col+1]) * m0;
            a[e+2] = (accP[e+2] + bias[col])   * sigm(accG[e+2] + bias[128 + col])   * m1;
            a[e+3] = (accP[e+3] + bias[col+1]) * sigm(accG[e+3] + bias[128 + col+1]) * m1;
        }

        // ===== pass P23: x = a * (zn@w_bp^T + b)*m * sig(zn@w_bg^T + b) =====
#pragma unroll
        for (int e = 0; e < 16; e++) { accP[e] = 0.f; accG[e] = 0.f; }
        mm_pair(accP, accG, aaddr0, W2, W3, l16, xv);
        {
            float s0 = 0.f, s20 = 0.f, s1 = 0.f, s21 = 0.f;
#pragma unroll
            for (int nb = 0; nb < 4; nb++) {
                int e = nb * 4, col = wc + nb * 8 + qt * 2;
                x[e]   = a[e]   * (accP[e]   + bias[256 + col])   * m0 * sigm(accG[e]   + bias[384 + col]);
                x[e+1] = a[e+1] * (accP[e+1] + bias[256 + col+1]) * m0 * sigm(accG[e+1] + bias[384 + col+1]);
                x[e+2] = a[e+2] * (accP[e+2] + bias[256 + col])   * m1 * sigm(accG[e+2] + bias[384 + col]);
                x[e+3] = a[e+3] * (accP[e+3] + bias[256 + col+1]) * m1 * sigm(accG[e+3] + bias[384 + col+1]);
                s0  += x[e] + x[e+1];   s20 += x[e]*x[e] + x[e+1]*x[e+1];
                s1  += x[e+2] + x[e+3]; s21 += x[e+2]*x[e+2] + x[e+3]*x[e+3];
            }
            s0  += __shfl_xor_sync(~0u, s0, 1);  s0  += __shfl_xor_sync(~0u, s0, 2);
            s20 += __shfl_xor_sync(~0u, s20, 1); s20 += __shfl_xor_sync(~0u, s20, 2);
            s1  += __shfl_xor_sync(~0u, s1, 1);  s1  += __shfl_xor_sync(~0u, s1, 2);
            s21 += __shfl_xor_sync(~0u, s21, 1); s21 += __shfl_xor_sync(~0u, s21, 2);
            if (qt == 0) {
                red[r0 * 4 + wcid] = make_float2(s0, s20);
                red[r1 * 4 + wcid] = make_float2(s1, s21);
            }
        }

        // ===== pass g: gate = sig(zn @ w_g^T + b_g) =====
#pragma unroll
        for (int e = 0; e < 16; e++) accG[e] = 0.f;
        mm1(accG, aaddr0, W4, l16, xv);
#pragma unroll
        for (int nb = 0; nb < 4; nb++) {
            int e = nb * 4, col = wc + nb * 8 + qt * 2;
            gate[e]   = sigm(accG[e]   + bias[512 + col]);
            gate[e+1] = sigm(accG[e+1] + bias[512 + col+1]);
            gate[e+2] = sigm(accG[e+2] + bias[512 + col]);
            gate[e+3] = sigm(accG[e+3] + bias[512 + col+1]);
        }
        __syncthreads();                       // S2: red complete; zn reads done

        // LN_out stats + xn -> zn buffer (fp16)
        {
            float sa = 0.f, sa2 = 0.f, sbv = 0.f, sb2 = 0.f;
#pragma unroll
            for (int k = 0; k < 4; k++) {
                float2 p = red[r0 * 4 + k]; sa += p.x; sa2 += p.y;
                float2 q2 = red[r1 * 4 + k]; sbv += q2.x; sb2 += q2.y;
            }
            float mu0 = sa * (1.f / 128);
            float rs0 = rsqrtf(fmaxf(sa2 * (1.f / 128) - mu0 * mu0, 0.f) + 1e-5f);
            float mu1 = sbv * (1.f / 128);
            float rs1 = rsqrtf(fmaxf(sb2 * (1.f / 128) - mu1 * mu1, 0.f) + 1e-5f);
#pragma unroll
            for (int nb = 0; nb < 4; nb++) {
                int e = nb * 4, col = wc + nb * 8 + qt * 2;
                float v0 = (x[e]   - mu0) * rs0 * bias[768 + col]   + bias[896 + col];
                float v1 = (x[e+1] - mu0) * rs0 * bias[768 + col+1] + bias[896 + col+1];
                float v2 = (x[e+2] - mu1) * rs1 * bias[768 + col]   + bias[896 + col];
                float v3 = (x[e+3] - mu1) * rs1 * bias[768 + col+1] + bias[896 + col+1];
                uint32_t p0 = ((uint32_t)__half_as_ushort(__float2half(v1)) << 16) |
                              __half_as_ushort(__float2half(v0));
                uint32_t p1 = ((uint32_t)__half_as_ushort(__float2half(v3)) << 16) |
                              __half_as_ushort(__float2half(v2));
                *(uint32_t*)(sm + OFF_ZN + (uint32_t)r0 * ZSTR + (uint32_t)col * 2u) = p0;
                *(uint32_t*)(sm + OFF_ZN + (uint32_t)r1 * ZSTR + (uint32_t)col * 2u) = p1;
            }
        }
        __syncthreads();                       // S3: xn visible

        // ===== pass z: out = (xn @ w_z^T + b_z) * gate =====
#pragma unroll
        for (int e = 0; e < 16; e++) accP[e] = 0.f;
        mm1(accP, aaddr0, W5, l16, xv);
        {
            float* o0 = out + (row0 + r0) * 128;
            float* o1 = out + (row0 + r1) * 128;
#pragma unroll
            for (int nb = 0; nb < 4; nb++) {
                int e = nb * 4, col = wc + nb * 8 + qt * 2;
                float2 u, v2;
                u.x  = (accP[e]   + bias[640 + col])   * gate[e];
                u.y  = (accP[e+1] + bias[640 + col+1]) * gate[e+1];
                v2.x = (accP[e+2] + bias[640 + col])   * gate[e+2];
                v2.y = (accP[e+3] + bias[640 + col+1]) * gate[e+3];
                *(float2*)(o0 + col) = u;
                *(float2*)(o1 + col) = v2;
            }
        }
        __syncthreads();                       // S4: zn reads done before next tile
    }
}

extern "C" void kernel_launch(void* const* d_in, const int* in_sizes, int n_in,
                              void* d_out, int out_size) {
    const float* z        = (const float*)d_in[0];
    const float* mask     = (const float*)d_in[1];
    const float* w_ap     = (const float*)d_in[2];
    const float* b_ap     = (const float*)d_in[3];
    const float* w_bp     = (const float*)d_in[4];
    const float* b_bp     = (const float*)d_in[5];
    const float* w_ag     = (const float*)d_in[6];
    const float* b_ag     = (const float*)d_in[7];
    const float* w_bg     = (const float*)d_in[8];
    const float* b_bg     = (const float*)d_in[9];
    const float* w_g      = (const float*)d_in[10];
    const float* b_g      = (const float*)d_in[11];
    const float* w_z      = (const float*)d_in[12];
    const float* b_z      = (const float*)d_in[13];
    const float* ln_in_w  = (const float*)d_in[14];
    const float* ln_in_b  = (const float*)d_in[15];
    const float* ln_out_w = (const float*)d_in[16];
    const float* ln_out_b = (const float*)d_in[17];
    float* out = (float*)d_out;

    const int rows = in_sizes[1];      // B*N*N
    const int ntiles = rows / 64;      // 2304

    static int nsm = 0;
    if (!nsm) {
        cudaFuncSetAttribute(tmu_kernel, cudaFuncAttributeMaxDynamicSharedMemorySize, SMEM_BYTES);
        if (cudaDeviceGetAttribute(&nsm, cudaDevAttrMultiProcessorCount, 0) != cudaSuccess || nsm <= 0)
            nsm = 148;
    }
    int grid = nsm < ntiles ? nsm : ntiles;

    // stage order in g_w: 0=w_ap 1=w_ag 2=w_bp 3=w_bg 4=w_g 5=w_z
    kPrep<<<6, 512>>>(w_ap, w_ag, w_bp, w_bg, w_g, w_z);
    tmu_kernel<<<grid, NT, SMEM_BYTES>>>(z, mask,
                                         b_ap, b_ag, b_bp, b_bg, b_g, b_z,
                                         ln_in_w, ln_in_b, ln_out_w, ln_out_b,
                                         out, ntiles);
}

// round 12
// speedup vs baseline: 1.0218x; 1.0218x over previous
#include <cuda_runtime.h>
#include <cuda_fp16.h>
#include <stdint.h>

// TriangleMultiplicativeUpdate — persistent-CTA fused kernel, round 11.
// mma.sync m16n8k16 fp16 (fp32 accum), single-pass fp16 weights, all six
// weights resident in smem (loaded once per CTA). Changes vs R10:
//  * (bp, bg, g) fused into ONE triple pass: A loaded once per k-step feeds
//    24 MMAs into 3 accumulator sets (12 independent chains -> latency hiding;
//    one whole pass boundary + epilogue removed).
//  * zn stored compact-swizzled (256B rows, XOR swizzle) like the weights.
// 3 passes + 4 barriers per 64-row tile.

#define NT 512

#define OFF_ZN  0u            // zn/xn: 64 x 256 fp16, swizzled
#define OFF_W0  16384u        // 6 weight slots, 32768B each, swizzled
#define WSLOT(i) (OFF_W0 + (uint32_t)(i) * 32768u)
#define OFF_SB  212992u       // 8 x 128 floats (biases, ln_out w/b)
#define OFF_MK  217088u       // 64 floats (mask)
#define OFF_RED 217344u       // 64 x 4 float2 (LN_out partials)
#define SMEM_BYTES 219392

// weights as fp16, SWIZZLED image: elem (n,c) at byte b^((b>>4)&0x70),
// b = n*256 + c*2.  0=w_ap 1=w_ag 2=w_bp 3=w_bg 4=w_g 5=w_z
__device__ __align__(16) __half g_w[6][128 * 128];

__device__ __forceinline__ uint32_t s2u(const void* p) {
    uint32_t a;
    asm("{ .reg .u64 t; cvta.to.shared.u64 t, %1; cvt.u32.u64 %0, t; }" : "=r"(a) : "l"(p));
    return a;
}

#define LDSM4(r, a) \
    asm volatile("ldmatrix.sync.aligned.m8n8.x4.shared.b16 {%0,%1,%2,%3}, [%4];" \
        : "=r"((r)[0]), "=r"((r)[1]), "=r"((r)[2]), "=r"((r)[3]) : "r"(a))

#define MMAOP(d, a, b0, b1) \
    asm volatile("mma.sync.aligned.m16n8k16.row.col.f32.f16.f16.f32 " \
        "{%0,%1,%2,%3}, {%4,%5,%6,%7}, {%8,%9}, {%0,%1,%2,%3};" \
        : "+f"((d)[0]), "+f"((d)[1]), "+f"((d)[2]), "+f"((d)[3]) \
        : "r"((a)[0]), "r"((a)[1]), "r"((a)[2]), "r"((a)[3]), "r"(b0), "r"(b1))

#define CPA16(dst, src) \
    asm volatile("cp.async.cg.shared.global [%0], [%1], 16;" :: "r"(dst), "l"(src))
#define CP_COMMIT() asm volatile("cp.async.commit_group;" ::: "memory")
#define CP_WAIT0()  asm volatile("cp.async.wait_group 0;" ::: "memory")

__device__ __forceinline__ float sigm(float x) { return 1.0f / (1.0f + __expf(-x)); }

// single pass: acc[16] += A(16x128) @ W^T (32 cols). A and W both swizzled.
__device__ __forceinline__ void mm1(float* acc, uint32_t azn, uint32_t l16a, uint32_t axv,
                                    uint32_t wb, uint32_t l16, uint32_t xv) {
#pragma unroll
    for (int k = 0; k < 8; k++) {
        uint32_t ko = (uint32_t)k * 32u;
        uint32_t offa = (ko + l16a) ^ axv;
        uint32_t offb = (ko + l16) ^ xv;
        uint32_t A[4], B0[4], B1[4];
        LDSM4(A, azn + offa);
        LDSM4(B0, wb + offb);
        LDSM4(B1, wb + offb + 4096u);
        MMAOP(acc + 0,  A, B0[0], B0[1]); MMAOP(acc + 4,  A, B0[2], B0[3]);
        MMAOP(acc + 8,  A, B1[0], B1[1]); MMAOP(acc + 12, A, B1[2], B1[3]);
    }
}

// paired pass: accP += A@Wp^T, accG += A@Wg^T
__device__ __forceinline__ void mm_pair(float* accP, float* accG,
                                        uint32_t azn, uint32_t l16a, uint32_t axv,
                                        uint32_t wpb, uint32_t wgb,
                                        uint32_t l16, uint32_t xv) {
#pragma unroll
    for (int k = 0; k < 8; k++) {
        uint32_t ko = (uint32_t)k * 32u;
        uint32_t offa = (ko + l16a) ^ axv;
        uint32_t offb = (ko + l16) ^ xv;
        uint32_t A[4], P0[4], P1[4], G0[4], G1[4];
        LDSM4(A, azn + offa);
        LDSM4(P0, wpb + offb); LDSM4(P1, wpb + offb + 4096u);
        LDSM4(G0, wgb + offb); LDSM4(G1, wgb + offb + 4096u);
        MMAOP(accP + 0,  A, P0[0], P0[1]); MMAOP(accP + 4,  A, P0[2], P0[3]);
        MMAOP(accP + 8,  A, P1[0], P1[1]); MMAOP(accP + 12, A, P1[2], P1[3]);
        MMAOP(accG + 0,  A, G0[0], G0[1]); MMAOP(accG + 4,  A, G0[2], G0[3]);
        MMAOP(accG + 8,  A, G1[0], G1[1]); MMAOP(accG + 12, A, G1[2], G1[3]);
    }
}

// triple pass: accP += A@Wp^T, accG += A@Wg^T, accH += A@Wh^T
__device__ __forceinline__ void mm_tri(float* accP, float* accG, float* accH,
                                       uint32_t azn, uint32_t l16a, uint32_t axv,
                                       uint32_t wpb, uint32_t wgb, uint32_t whb,
                                       uint32_t l16, uint32_t xv) {
#pragma unroll
    for (int k = 0; k < 8; k++) {
        uint32_t ko = (uint32_t)k * 32u;
        uint32_t offa = (ko + l16a) ^ axv;
        uint32_t offb = (ko + l16) ^ xv;
        uint32_t A[4], P0[4], P1[4], G0[4], G1[4], H0[4], H1[4];
        LDSM4(A, azn + offa);
        LDSM4(P0, wpb + offb); LDSM4(P1, wpb + offb + 4096u);
        LDSM4(G0, wgb + offb); LDSM4(G1, wgb + offb + 4096u);
        LDSM4(H0, whb + offb); LDSM4(H1, whb + offb + 4096u);
        MMAOP(accP + 0,  A, P0[0], P0[1]); MMAOP(accP + 4,  A, P0[2], P0[3]);
        MMAOP(accP + 8,  A, P1[0], P1[1]); MMAOP(accP + 12, A, P1[2], P1[3]);
        MMAOP(accG + 0,  A, G0[0], G0[1]); MMAOP(accG + 4,  A, G0[2], G0[3]);
        MMAOP(accG + 8,  A, G1[0], G1[1]); MMAOP(accG + 12, A, G1[2], G1[3]);
        MMAOP(accH + 0,  A, H0[0], H0[1]); MMAOP(accH + 4,  A, H0[2], H0[3]);
        MMAOP(accH + 8,  A, H1[0], H1[1]); MMAOP(accH + 12, A, H1[2], H1[3]);
    }
}

__global__ void kPrep(const float* __restrict__ w0, const float* __restrict__ w1,
                      const float* __restrict__ w2, const float* __restrict__ w3,
                      const float* __restrict__ w4, const float* __restrict__ w5) {
    const float* w;
    switch (blockIdx.x) {
        case 0: w = w0; break; case 1: w = w1; break; case 2: w = w2; break;
        case 3: w = w3; break; case 4: w = w4; break; default: w = w5; break;
    }
    char* img = (char*)g_w[blockIdx.x];
    for (int i = threadIdx.x; i < 128 * 128; i += blockDim.x) {
        int n = i >> 7, c = i & 127;
        uint32_t b = (uint32_t)n * 256u + (uint32_t)c * 2u;
        uint32_t sw = b ^ ((b >> 4) & 0x70u);
        *(__half*)(img + sw) = __float2half(__ldg(w + i));
    }
}

__global__ void __launch_bounds__(NT, 1)
tmu_kernel(const float* __restrict__ z, const float* __restrict__ mask,
           const float* __restrict__ b_ap, const float* __restrict__ b_ag,
           const float* __restrict__ b_bp, const float* __restrict__ b_bg,
           const float* __restrict__ b_g,  const float* __restrict__ b_z,
           const float* __restrict__ ln_in_w,  const float* __restrict__ ln_in_b,
           const float* __restrict__ ln_out_w, const float* __restrict__ ln_out_b,
           float* __restrict__ out, int ntiles) {
    extern __shared__ char sm[];
    const uint32_t smb = s2u(sm);
    const int t = threadIdx.x;
    const int w = t >> 5, lid = t & 31;
    const int quad = lid >> 2, qt = lid & 3;
    const int wr = (w & 3) * 16;          // 4 row-warps x 16 rows
    const int wc = (w >> 2) * 32;         // 4 col-warps x 32 cols
    const int wcid = w >> 2;
    const int r0 = wr + quad, r1 = r0 + 8;

    float* bias = (float*)(sm + OFF_SB);
    float* mk   = (float*)(sm + OFF_MK);
    float2* red = (float2*)(sm + OFF_RED);

    // ---- load ALL SIX weights once (swizzled images copied linearly) ----
#pragma unroll
    for (int m = 0; m < 6; m++) {
        const char* s = (const char*)g_w[m];
#pragma unroll
        for (int i = 0; i < 4; i++) {
            int cid = t + i * NT;          // 2048 16B chunks per matrix
            CPA16(smb + WSLOT(m) + (uint32_t)cid * 16u, s + (size_t)cid * 16);
        }
    }
    CP_COMMIT();

    if (t < 128) {
        bias[t] = __ldg(b_ap + t);           bias[128 + t] = __ldg(b_ag + t);
        bias[256 + t] = __ldg(b_bp + t);     bias[384 + t] = __ldg(b_bg + t);
        bias[512 + t] = __ldg(b_g + t);      bias[640 + t] = __ldg(b_z + t);
        bias[768 + t] = __ldg(ln_out_w + t); bias[896 + t] = __ldg(ln_out_b + t);
    }

    // per-warp/lane ldmatrix constants (both operands swizzled-compact)
    const uint32_t azn = smb + OFF_ZN + (uint32_t)(wr + (lid & 15)) * 256u;
    const uint32_t l16a = (uint32_t)(lid >> 4) * 16u;
    const uint32_t axv = (uint32_t)(lid & 7) << 4;     // ((row)&7)<<4, wr%16==0
    const int n_lane = wc + (lid & 7) + ((lid >> 4) << 3);
    const uint32_t l16 = (uint32_t)((lid >> 3) & 1) * 16u;
    const uint32_t xv = (uint32_t)(n_lane & 7) << 4;
    const uint32_t wnl = (uint32_t)n_lane * 256u;
    const uint32_t W0 = smb + WSLOT(0) + wnl, W1 = smb + WSLOT(1) + wnl;
    const uint32_t W2 = smb + WSLOT(2) + wnl, W3 = smb + WSLOT(3) + wnl;
    const uint32_t W4 = smb + WSLOT(4) + wnl, W5 = smb + WSLOT(5) + wnl;

    CP_WAIT0();   // weights landed (visibility via first __syncthreads)

    for (int tile = blockIdx.x; tile < ntiles; tile += gridDim.x) {
        const size_t row0 = (size_t)tile * 64;

        // ---- LN_in: 8 threads/row over 64 rows; write zn fp16 swizzled ----
        {
            const int r = t >> 3, q = t & 7;
            const uint32_t rxv = (uint32_t)(r & 7) << 4;
            const float* zr = z + (row0 + r) * 128 + q * 16;
            float v[16], s = 0.f, s2 = 0.f;
#pragma unroll
            for (int i = 0; i < 4; i++) {
                float4 f = __ldg((const float4*)(zr + 4 * i));
                v[4*i] = f.x; v[4*i+1] = f.y; v[4*i+2] = f.z; v[4*i+3] = f.w;
                s += f.x + f.y + f.z + f.w;
                s2 += f.x*f.x + f.y*f.y + f.z*f.z + f.w*f.w;
            }
            s  += __shfl_xor_sync(~0u, s, 1);  s  += __shfl_xor_sync(~0u, s, 2);
            s  += __shfl_xor_sync(~0u, s, 4);
            s2 += __shfl_xor_sync(~0u, s2, 1); s2 += __shfl_xor_sync(~0u, s2, 2);
            s2 += __shfl_xor_sync(~0u, s2, 4);
            float mu = s * (1.f / 128);
            float rstd = rsqrtf(fmaxf(s2 * (1.f / 128) - mu * mu, 0.f) + 1e-5f);
#pragma unroll
            for (int j = 0; j < 2; j++) {
                union { uint4 u; __half b[8]; } H;
#pragma unroll
                for (int i = 0; i < 8; i++) {
                    int c = q * 16 + j * 8 + i;
                    float f = (v[j*8+i] - mu) * rstd * __ldg(ln_in_w + c) + __ldg(ln_in_b + c);
                    H.b[i] = __float2half(f);
                }
                uint32_t o = ((uint32_t)(q * 2 + j) * 16u) ^ rxv;
                *(uint4*)(sm + OFF_ZN + (uint32_t)r * 256u + o) = H.u;
            }
            if (q == 0) mk[r] = __ldg(mask + row0 + r);
        }
        __syncthreads();                       // S1: zn + mk visible (+W on iter 0)

        float a[16], x[16], gate[16], accP[16], accG[16], accH[16];
        const float m0 = mk[r0], m1 = mk[r1];

        // ===== pass P01: accP = zn@w_ap^T, accG = zn@w_ag^T; a in regs =====
#pragma unroll
        for (int e = 0; e < 16; e++) { accP[e] = 0.f; accG[e] = 0.f; }
        mm_pair(accP, accG, azn, l16a, axv, W0, W1, l16, xv);
#pragma unroll
        for (int nb = 0; nb < 4; nb++) {
            int e = nb * 4, col = wc + nb * 8 + qt * 2;
            a[e]   = (accP[e]   + bias[col])   * sigm(accG[e]   + bias[128 + col])   * m0;
            a[e+1] = (accP[e+1] + bias[col+1]) * sigm(accG[e+1] + bias[128 + col+1]) * m0;
            a[e+2] = (accP[e+2] + bias[col])   * sigm(accG[e+2] + bias[128 + col])   * m1;
            a[e+3] = (accP[e+3] + bias[col+1]) * sigm(accG[e+3] + bias[128 + col+1]) * m1;
        }

        // ===== pass P234 (triple): bp -> accP, bg -> accG, g -> accH =====
#pragma unroll
        for (int e = 0; e < 16; e++) { accP[e] = 0.f; accG[e] = 0.f; accH[e] = 0.f; }
        mm_tri(accP, accG, accH, azn, l16a, axv, W2, W3, W4, l16, xv);
        {
            float s0 = 0.f, s20 = 0.f, s1 = 0.f, s21 = 0.f;
#pragma unroll
            for (int nb = 0; nb < 4; nb++) {
                int e = nb * 4, col = wc + nb * 8 + qt * 2;
                x[e]   = a[e]   * (accP[e]   + bias[256 + col])   * m0 * sigm(accG[e]   + bias[384 + col]);
                x[e+1] = a[e+1] * (accP[e+1] + bias[256 + col+1]) * m0 * sigm(accG[e+1] + bias[384 + col+1]);
                x[e+2] = a[e+2] * (accP[e+2] + bias[256 + col])   * m1 * sigm(accG[e+2] + bias[384 + col]);
                x[e+3] = a[e+3] * (accP[e+3] + bias[256 + col+1]) * m1 * sigm(accG[e+3] + bias[384 + col+1]);
                s0  += x[e] + x[e+1];   s20 += x[e]*x[e] + x[e+1]*x[e+1];
                s1  += x[e+2] + x[e+3]; s21 += x[e+2]*x[e+2] + x[e+3]*x[e+3];
                gate[e]   = sigm(accH[e]   + bias[512 + col]);
                gate[e+1] = sigm(accH[e+1] + bias[512 + col+1]);
                gate[e+2] = sigm(accH[e+2] + bias[512 + col]);
                gate[e+3] = sigm(accH[e+3] + bias[512 + col+1]);
            }
            s0  += __shfl_xor_sync(~0u, s0, 1);  s0  += __shfl_xor_sync(~0u, s0, 2);
            s20 += __shfl_xor_sync(~0u, s20, 1); s20 += __shfl_xor_sync(~0u, s20, 2);
            s1  += __shfl_xor_sync(~0u, s1, 1);  s1  += __shfl_xor_sync(~0u, s1, 2);
            s21 += __shfl_xor_sync(~0u, s21, 1); s21 += __shfl_xor_sync(~0u, s21, 2);
            if (qt == 0) {
                red[r0 * 4 + wcid] = make_float2(s0, s20);
                red[r1 * 4 + wcid] = make_float2(s1, s21);
            }
        }
        __syncthreads();                       // S2: red complete; zn reads done

        // LN_out stats + xn -> zn buffer (fp16, swizzled)
        {
            float sa = 0.f, sa2 = 0.f, sbv = 0.f, sb2 = 0.f;
#pragma unroll
            for (int k = 0; k < 4; k++) {
                float2 p = red[r0 * 4 + k]; sa += p.x; sa2 += p.y;
                float2 q2 = red[r1 * 4 + k]; sbv += q2.x; sb2 += q2.y;
            }
            float mu0 = sa * (1.f / 128);
            float rs0 = rsqrtf(fmaxf(sa2 * (1.f / 128) - mu0 * mu0, 0.f) + 1e-5f);
            float mu1 = sbv * (1.f / 128);
            float rs1 = rsqrtf(fmaxf(sb2 * (1.f / 128) - mu1 * mu1, 0.f) + 1e-5f);
            const uint32_t x0v = (uint32_t)(r0 & 7) << 4;
            const uint32_t x1v = (uint32_t)(r1 & 7) << 4;
#pragma unroll
            for (int nb = 0; nb < 4; nb++) {
                int e = nb * 4, col = wc + nb * 8 + qt * 2;
                float v0 = (x[e]   - mu0) * rs0 * bias[768 + col]   + bias[896 + col];
                float v1 = (x[e+1] - mu0) * rs0 * bias[768 + col+1] + bias[896 + col+1];
                float v2 = (x[e+2] - mu1) * rs1 * bias[768 + col]   + bias[896 + col];
                float v3 = (x[e+3] - mu1) * rs1 * bias[768 + col+1] + bias[896 + col+1];
                uint32_t p0 = ((uint32_t)__half_as_ushort(__float2half(v1)) << 16) |
                              __half_as_ushort(__float2half(v0));
                uint32_t p1 = ((uint32_t)__half_as_ushort(__float2half(v3)) << 16) |
                              __half_as_ushort(__float2half(v2));
                uint32_t cb = (uint32_t)col * 2u;
                *(uint32_t*)(sm + OFF_ZN + (uint32_t)r0 * 256u + (cb ^ x0v)) = p0;
                *(uint32_t*)(sm + OFF_ZN + (uint32_t)r1 * 256u + (cb ^ x1v)) = p1;
            }
        }
        __syncthreads();                       // S3: xn visible

        // ===== pass z: out = (xn @ w_z^T + b_z) * gate =====
#pragma unroll
        for (int e = 0; e < 16; e++) accP[e] = 0.f;
        mm1(accP, azn, l16a, axv, W5, l16, xv);
        {
            float* o0 = out + (row0 + r0) * 128;
            float* o1 = out + (row0 + r1) * 128;
#pragma unroll
            for (int nb = 0; nb < 4; nb++) {
                int e = nb * 4, col = wc + nb * 8 + qt * 2;
                float2 u, v2;
                u.x  = (accP[e]   + bias[640 + col])   * gate[e];
                u.y  = (accP[e+1] + bias[640 + col+1]) * gate[e+1];
                v2.x = (accP[e+2] + bias[640 + col])   * gate[e+2];
                v2.y = (accP[e+3] + bias[640 + col+1]) * gate[e+3];
                *(float2*)(o0 + col) = u;
                *(float2*)(o1 + col) = v2;
            }
        }
        __syncthreads();                       // S4: zn reads done before next tile
    }
}

extern "C" void kernel_launch(void* const* d_in, const int* in_sizes, int n_in,
                              void* d_out, int out_size) {
    const float* z        = (const float*)d_in[0];
    const float* mask     = (const float*)d_in[1];
    const float* w_ap     = (const float*)d_in[2];
    const float* b_ap     = (const float*)d_in[3];
    const float* w_bp     = (const float*)d_in[4];
    const float* b_bp     = (const float*)d_in[5];
    const float* w_ag     = (const float*)d_in[6];
    const float* b_ag     = (const float*)d_in[7];
    const float* w_bg     = (const float*)d_in[8];
    const float* b_bg     = (const float*)d_in[9];
    const float* w_g      = (const float*)d_in[10];
    const float* b_g      = (const float*)d_in[11];
    const float* w_z      = (const float*)d_in[12];
    const float* b_z      = (const float*)d_in[13];
    const float* ln_in_w  = (const float*)d_in[14];
    const float* ln_in_b  = (const float*)d_in[15];
    const float* ln_out_w = (const float*)d_in[16];
    const float* ln_out_b = (const float*)d_in[17];
    float* out = (float*)d_out;

    const int rows = in_sizes[1];      // B*N*N
    const int ntiles = rows / 64;      // 2304

    static int nsm = 0;
    if (!nsm) {
        cudaFuncSetAttribute(tmu_kernel, cudaFuncAttributeMaxDynamicSharedMemorySize, SMEM_BYTES);
        if (cudaDeviceGetAttribute(&nsm, cudaDevAttrMultiProcessorCount, 0) != cudaSuccess || nsm <= 0)
            nsm = 148;
    }
    int grid = nsm < ntiles ? nsm : ntiles;

    // stage order in g_w: 0=w_ap 1=w_ag 2=w_bp 3=w_bg 4=w_g 5=w_z
    kPrep<<<6, 512>>>(w_ap, w_ag, w_bp, w_bg, w_g, w_z);
    tmu_kernel<<<grid, NT, SMEM_BYTES>>>(z, mask,
                                         b_ap, b_ag, b_bp, b_bg, b_g, b_z,
                                         ln_in_w, ln_in_b, ln_out_w, ln_out_b,
                                         out, ntiles);
}

// round 13
// speedup vs baseline: 1.0527x; 1.0302x over previous
#include <cuda_runtime.h>
#include <cuda_fp16.h>
#include <stdint.h>

// TriangleMultiplicativeUpdate — persistent single-launch kernel, round 12.
// mma.sync m16n8k16 fp16 (fp32 accum), single-pass fp16 weights, all six
// weights resident in smem, converted in-kernel from fp32 (no prep launch).
// zn DOUBLE-buffered: next tile's LN_in overlaps current tile's tail, with
// prefetch.global.L2 issued one full tile ahead. 3 barriers/tile. Biases &
// mask fp16; LN_out stats via smem atomics (512B).

#define NT 512

#define OFF_ZN   0u                 // zn/xn: 2 x (64 x 256B fp16, swizzled)
#define OFF_W0   32768u             // 6 weight slots, 32768B each, swizzled
#define WSLOT(i) (OFF_W0 + (uint32_t)(i) * 32768u)
#define OFF_SB   229376u            // 8 x 128 __half (biases, ln_out w/b)
#define OFF_MK   231424u            // 2 x 64 __half (mask per buffer)
#define OFF_RED  231680u            // 64 x float2 (LN_out partials, atomics)
#define SMEM_BYTES 232192

__device__ __forceinline__ uint32_t s2u(const void* p) {
    uint32_t a;
    asm("{ .reg .u64 t; cvta.to.shared.u64 t, %1; cvt.u32.u64 %0, t; }" : "=r"(a) : "l"(p));
    return a;
}
__device__ __forceinline__ uint32_t f16x2(float lo, float hi) {
    uint32_t r;
    asm("cvt.rn.f16x2.f32 %0, %1, %2;" : "=r"(r) : "f"(hi), "f"(lo));
    return r;
}

#define LDSM4(r, a) \
    asm volatile("ldmatrix.sync.aligned.m8n8.x4.shared.b16 {%0,%1,%2,%3}, [%4];" \
        : "=r"((r)[0]), "=r"((r)[1]), "=r"((r)[2]), "=r"((r)[3]) : "r"(a))

#define MMAOP(d, a, b0, b1) \
    asm volatile("mma.sync.aligned.m16n8k16.row.col.f32.f16.f16.f32 " \
        "{%0,%1,%2,%3}, {%4,%5,%6,%7}, {%8,%9}, {%0,%1,%2,%3};" \
        : "+f"((d)[0]), "+f"((d)[1]), "+f"((d)[2]), "+f"((d)[3]) \
        : "r"((a)[0]), "r"((a)[1]), "r"((a)[2]), "r"((a)[3]), "r"(b0), "r"(b1))

__device__ __forceinline__ float sigm(float x) { return 1.0f / (1.0f + __expf(-x)); }

// single pass: acc[16] += A(16x128) @ W^T (32 cols); A and W swizzled-compact.
__device__ __forceinline__ void mm1(float* acc, uint32_t azn, uint32_t l16a, uint32_t axv,
                                    uint32_t wb, uint32_t l16, uint32_t xv) {
#pragma unroll
    for (int k = 0; k < 8; k++) {
        uint32_t ko = (uint32_t)k * 32u;
        uint32_t offa = (ko + l16a) ^ axv;
        uint32_t offb = (ko + l16) ^ xv;
        uint32_t A[4], B0[4], B1[4];
        LDSM4(A, azn + offa);
        LDSM4(B0, wb + offb);
        LDSM4(B1, wb + offb + 4096u);
        MMAOP(acc + 0,  A, B0[0], B0[1]); MMAOP(acc + 4,  A, B0[2], B0[3]);
        MMAOP(acc + 8,  A, B1[0], B1[1]); MMAOP(acc + 12, A, B1[2], B1[3]);
    }
}

// paired pass
__device__ __forceinline__ void mm_pair(float* accP, float* accG,
                                        uint32_t azn, uint32_t l16a, uint32_t axv,
                                        uint32_t wpb, uint32_t wgb,
                                        uint32_t l16, uint32_t xv) {
#pragma unroll
    for (int k = 0; k < 8; k++) {
        uint32_t ko = (uint32_t)k * 32u;
        uint32_t offa = (ko + l16a) ^ axv;
        uint32_t offb = (ko + l16) ^ xv;
        uint32_t A[4], P0[4], P1[4], G0[4], G1[4];
        LDSM4(A, azn + offa);
        LDSM4(P0, wpb + offb); LDSM4(P1, wpb + offb + 4096u);
        LDSM4(G0, wgb + offb); LDSM4(G1, wgb + offb + 4096u);
        MMAOP(accP + 0,  A, P0[0], P0[1]); MMAOP(accP + 4,  A, P0[2], P0[3]);
        MMAOP(accP + 8,  A, P1[0], P1[1]); MMAOP(accP + 12, A, P1[2], P1[3]);
        MMAOP(accG + 0,  A, G0[0], G0[1]); MMAOP(accG + 4,  A, G0[2], G0[3]);
        MMAOP(accG + 8,  A, G1[0], G1[1]); MMAOP(accG + 12, A, G1[2], G1[3]);
    }
}

// triple pass
__device__ __forceinline__ void mm_tri(float* accP, float* accG, float* accH,
                                       uint32_t azn, uint32_t l16a, uint32_t axv,
                                       uint32_t wpb, uint32_t wgb, uint32_t whb,
                                       uint32_t l16, uint32_t xv) {
#pragma unroll
    for (int k = 0; k < 8; k++) {
        uint32_t ko = (uint32_t)k * 32u;
        uint32_t offa = (ko + l16a) ^ axv;
        uint32_t offb = (ko + l16) ^ xv;
        uint32_t A[4], P0[4], P1[4], G0[4], G1[4], H0[4], H1[4];
        LDSM4(A, azn + offa);
        LDSM4(P0, wpb + offb); LDSM4(P1, wpb + offb + 4096u);
        LDSM4(G0, wgb + offb); LDSM4(G1, wgb + offb + 4096u);
        LDSM4(H0, whb + offb); LDSM4(H1, whb + offb + 4096u);
        MMAOP(accP + 0,  A, P0[0], P0[1]); MMAOP(accP + 4,  A, P0[2], P0[3]);
        MMAOP(accP + 8,  A, P1[0], P1[1]); MMAOP(accP + 12, A, P1[2], P1[3]);
        MMAOP(accG + 0,  A, G0[0], G0[1]); MMAOP(accG + 4,  A, G0[2], G0[3]);
        MMAOP(accG + 8,  A, G1[0], G1[1]); MMAOP(accG + 12, A, G1[2], G1[3]);
        MMAOP(accH + 0,  A, H0[0], H0[1]); MMAOP(accH + 4,  A, H0[2], H0[3]);
        MMAOP(accH + 8,  A, H1[0], H1[1]); MMAOP(accH + 12, A, H1[2], H1[3]);
    }
}

// LN_in for one 64-row tile into zn buffer `bufoff`; 8 threads/row.
__device__ __forceinline__ void ln_in_tile(char* sm, const float* z,
                                           const float* mask,
                                           const float* ln_in_w, const float* ln_in_b,
                                           size_t row0, uint32_t bufoff,
                                           __half* mkh, int t) {
    const int r = t >> 3, q = t & 7;
    const uint32_t rxv = (uint32_t)(r & 7) << 4;
    const float* zr = z + (row0 + r) * 128 + q * 16;
    float v[16], s = 0.f, s2 = 0.f;
#pragma unroll
    for (int i = 0; i < 4; i++) {
        float4 f = __ldg((const float4*)(zr + 4 * i));
        v[4*i] = f.x; v[4*i+1] = f.y; v[4*i+2] = f.z; v[4*i+3] = f.w;
        s += f.x + f.y + f.z + f.w;
        s2 += f.x*f.x + f.y*f.y + f.z*f.z + f.w*f.w;
    }
    s  += __shfl_xor_sync(~0u, s, 1);  s  += __shfl_xor_sync(~0u, s, 2);
    s  += __shfl_xor_sync(~0u, s, 4);
    s2 += __shfl_xor_sync(~0u, s2, 1); s2 += __shfl_xor_sync(~0u, s2, 2);
    s2 += __shfl_xor_sync(~0u, s2, 4);
    float mu = s * (1.f / 128);
    float rstd = rsqrtf(fmaxf(s2 * (1.f / 128) - mu * mu, 0.f) + 1e-5f);
#pragma unroll
    for (int j = 0; j < 2; j++) {
        uint32_t h[4];
#pragma unroll
        for (int i = 0; i < 4; i++) {
            int c = q * 16 + j * 8 + i * 2;
            float f0 = (v[j*8+i*2]   - mu) * rstd * __ldg(ln_in_w + c)   + __ldg(ln_in_b + c);
            float f1 = (v[j*8+i*2+1] - mu) * rstd * __ldg(ln_in_w + c+1) + __ldg(ln_in_b + c+1);
            h[i] = f16x2(f0, f1);
        }
        uint32_t o = ((uint32_t)(q * 2 + j) * 16u) ^ rxv;
        *(uint4*)(sm + OFF_ZN + bufoff + (uint32_t)r * 256u + o) =
            make_uint4(h[0], h[1], h[2], h[3]);
    }
    if (q == 0) mkh[r] = __float2half(__ldg(mask + row0 + r));
}

__global__ void __launch_bounds__(NT, 1)
tmu_kernel(const float* __restrict__ z, const float* __restrict__ mask,
           const float* __restrict__ w_ap, const float* __restrict__ b_ap,
           const float* __restrict__ w_bp, const float* __restrict__ b_bp,
           const float* __restrict__ w_ag, const float* __restrict__ b_ag,
           const float* __restrict__ w_bg, const float* __restrict__ b_bg,
           const float* __restrict__ w_g,  const float* __restrict__ b_g,
           const float* __restrict__ w_z,  const float* __restrict__ b_z,
           const float* __restrict__ ln_in_w,  const float* __restrict__ ln_in_b,
           const float* __restrict__ ln_out_w, const float* __restrict__ ln_out_b,
           float* __restrict__ out, int ntiles) {
    extern __shared__ char sm[];
    const uint32_t smb = s2u(sm);
    const int t = threadIdx.x;
    const int w = t >> 5, lid = t & 31;
    const int quad = lid >> 2, qt = lid & 3;
    const int wr = (w & 3) * 16;
    const int wc = (w >> 2) * 32;
    const int r0 = wr + quad, r1 = r0 + 8;

    __half* bh  = (__half*)(sm + OFF_SB);
    __half* mkh = (__half*)(sm + OFF_MK);
    float*  red = (float*)(sm + OFF_RED);    // [64][2] sum, sumsq

    // ---- in-kernel weight prep: fp32 global -> fp16 swizzled smem ----
#pragma unroll
    for (int m = 0; m < 6; m++) {
        const float* wp = (m == 0) ? w_ap : (m == 1) ? w_ag : (m == 2) ? w_bp :
                          (m == 3) ? w_bg : (m == 4) ? w_g : w_z;
        const float4* src = (const float4*)wp;
#pragma unroll
        for (int i = 0; i < 4; i++) {
            int cid = t + i * NT;              // 2048 16B-dst chunks
            int n = cid >> 4, c8 = cid & 15;   // row, 8-col chunk
            float4 f0 = __ldg(src + n * 32 + c8 * 2);
            float4 f1 = __ldg(src + n * 32 + c8 * 2 + 1);
            uint4 hv = make_uint4(f16x2(f0.x, f0.y), f16x2(f0.z, f0.w),
                                  f16x2(f1.x, f1.y), f16x2(f1.z, f1.w));
            uint32_t off = WSLOT(m) + (uint32_t)n * 256u +
                           (((uint32_t)c8 * 16u) ^ (((uint32_t)n & 7u) << 4));
            *(uint4*)(sm + off) = hv;
        }
    }
    // biases (fp16) + red zero
    if (t < 128) {
        bh[t]       = __float2half(__ldg(b_ap + t));
        bh[128 + t] = __float2half(__ldg(b_ag + t));
        bh[256 + t] = __float2half(__ldg(b_bp + t));
        bh[384 + t] = __float2half(__ldg(b_bg + t));
        bh[512 + t] = __float2half(__ldg(b_g + t));
        bh[640 + t] = __float2half(__ldg(b_z + t));
        bh[768 + t] = __float2half(__ldg(ln_out_w + t));
        bh[896 + t] = __float2half(__ldg(ln_out_b + t));
        red[t] = 0.f;
    }

    // per-warp/lane ldmatrix constants
    const uint32_t arow = (uint32_t)(wr + (lid & 15)) * 256u;
    const uint32_t l16a = (uint32_t)(lid >> 4) * 16u;
    const uint32_t axv = (uint32_t)(lid & 7) << 4;
    const int n_lane = wc + (lid & 7) + ((lid >> 4) << 3);
    const uint32_t l16 = (uint32_t)((lid >> 3) & 1) * 16u;
    const uint32_t xv = (uint32_t)(n_lane & 7) << 4;
    const uint32_t wnl = (uint32_t)n_lane * 256u;
    const uint32_t W0 = smb + WSLOT(0) + wnl, W1 = smb + WSLOT(1) + wnl;
    const uint32_t W2 = smb + WSLOT(2) + wnl, W3 = smb + WSLOT(3) + wnl;
    const uint32_t W4 = smb + WSLOT(4) + wnl, W5 = smb + WSLOT(5) + wnl;

    const int tile0 = blockIdx.x;
    if (tile0 >= ntiles) return;

    // prologue: stage first tile into buffer 0
    ln_in_tile(sm, z, mask, ln_in_w, ln_in_b, (size_t)tile0 * 64, 0u, mkh, t);
    __syncthreads();                           // S0: weights + zn[0] + bias visible

    int it = 0;
    for (int tile = tile0; tile < ntiles; tile += gridDim.x, it++) {
        const size_t row0 = (size_t)tile * 64;
        const uint32_t cur = (uint32_t)(it & 1) * 16384u;
        const uint32_t nxtb = cur ^ 16384u;
        const int ntile = tile + gridDim.x;
        __half* mkc = mkh + (it & 1) * 64;

        // L2 prefetch of next z tile (32KB = 512 thr x 64B)
        if (ntile < ntiles) {
            const char* zp = (const char*)(z + (size_t)ntile * 64 * 128) + t * 64;
            asm volatile("prefetch.global.L2 [%0];" :: "l"(zp));
        }

        const uint32_t azn = smb + OFF_ZN + cur + arow;
        float a[16], x[16], gate[16], accP[16], accG[16], accH[16];
        const float m0 = __half2float(mkc[r0]), m1 = __half2float(mkc[r1]);

        // ===== P01: accP = zn@w_ap^T, accG = zn@w_ag^T -> a =====
#pragma unroll
        for (int e = 0; e < 16; e++) { accP[e] = 0.f; accG[e] = 0.f; }
        mm_pair(accP, accG, azn, l16a, axv, W0, W1, l16, xv);
#pragma unroll
        for (int nb = 0; nb < 4; nb++) {
            int e = nb * 4, col = wc + nb * 8 + qt * 2;
            float2 bp = __half22float2(*(__half2*)(bh + col));
            float2 bg = __half22float2(*(__half2*)(bh + 128 + col));
            a[e]   = (accP[e]   + bp.x) * sigm(accG[e]   + bg.x) * m0;
            a[e+1] = (accP[e+1] + bp.y) * sigm(accG[e+1] + bg.y) * m0;
            a[e+2] = (accP[e+2] + bp.x) * sigm(accG[e+2] + bg.x) * m1;
            a[e+3] = (accP[e+3] + bp.y) * sigm(accG[e+3] + bg.y) * m1;
        }

        // ===== P234 (triple): bp, bg, g =====
#pragma unroll
        for (int e = 0; e < 16; e++) { accP[e] = 0.f; accG[e] = 0.f; accH[e] = 0.f; }
        mm_tri(accP, accG, accH, azn, l16a, axv, W2, W3, W4, l16, xv);
        {
            float s0 = 0.f, s20 = 0.f, s1 = 0.f, s21 = 0.f;
#pragma unroll
            for (int nb = 0; nb < 4; nb++) {
                int e = nb * 4, col = wc + nb * 8 + qt * 2;
                float2 bp = __half22float2(*(__half2*)(bh + 256 + col));
                float2 bg = __half22float2(*(__half2*)(bh + 384 + col));
                float2 bgg = __half22float2(*(__half2*)(bh + 512 + col));
                x[e]   = a[e]   * (accP[e]   + bp.x) * m0 * sigm(accG[e]   + bg.x);
                x[e+1] = a[e+1] * (accP[e+1] + bp.y) * m0 * sigm(accG[e+1] + bg.y);
                x[e+2] = a[e+2] * (accP[e+2] + bp.x) * m1 * sigm(accG[e+2] + bg.x);
                x[e+3] = a[e+3] * (accP[e+3] + bp.y) * m1 * sigm(accG[e+3] + bg.y);
                s0  += x[e] + x[e+1];   s20 += x[e]*x[e] + x[e+1]*x[e+1];
                s1  += x[e+2] + x[e+3]; s21 += x[e+2]*x[e+2] + x[e+3]*x[e+3];
                gate[e]   = sigm(accH[e]   + bgg.x);
                gate[e+1] = sigm(accH[e+1] + bgg.y);
                gate[e+2] = sigm(accH[e+2] + bgg.x);
                gate[e+3] = sigm(accH[e+3] + bgg.y);
            }
            s0  += __shfl_xor_sync(~0u, s0, 1);  s0  += __shfl_xor_sync(~0u, s0, 2);
            s20 += __shfl_xor_sync(~0u, s20, 1); s20 += __shfl_xor_sync(~0u, s20, 2);
            s1  += __shfl_xor_sync(~0u, s1, 1);  s1  += __shfl_xor_sync(~0u, s1, 2);
            s21 += __shfl_xor_sync(~0u, s21, 1); s21 += __shfl_xor_sync(~0u, s21, 2);
            if (qt == 0) {
                atomicAdd(red + 2 * r0,     s0);
                atomicAdd(red + 2 * r0 + 1, s20);
                atomicAdd(red + 2 * r1,     s1);
                atomicAdd(red + 2 * r1 + 1, s21);
            }
        }
        __syncthreads();                       // S2: zn reads done; atomics drained

        // LN_out stats + xn -> zn[cur] (fp16, swizzled)
        {
            float sa = red[2*r0], sa2 = red[2*r0+1];
            float sb = red[2*r1], sb2 = red[2*r1+1];
            float mu0 = sa * (1.f / 128);
            float rs0 = rsqrtf(fmaxf(sa2 * (1.f / 128) - mu0 * mu0, 0.f) + 1e-5f);
            float mu1 = sb * (1.f / 128);
            float rs1 = rsqrtf(fmaxf(sb2 * (1.f / 128) - mu1 * mu1, 0.f) + 1e-5f);
            const uint32_t x0v = (uint32_t)(r0 & 7) << 4;
            const uint32_t x1v = (uint32_t)(r1 & 7) << 4;
#pragma unroll
            for (int nb = 0; nb < 4; nb++) {
                int e = nb * 4, col = wc + nb * 8 + qt * 2;
                float2 lw = __half22float2(*(__half2*)(bh + 768 + col));
                float2 lb = __half22float2(*(__half2*)(bh + 896 + col));
                float v0 = (x[e]   - mu0) * rs0 * lw.x + lb.x;
                float v1 = (x[e+1] - mu0) * rs0 * lw.y + lb.y;
                float v2 = (x[e+2] - mu1) * rs1 * lw.x + lb.x;
                float v3 = (x[e+3] - mu1) * rs1 * lw.y + lb.y;
                uint32_t cb = (uint32_t)col * 2u;
                *(uint32_t*)(sm + OFF_ZN + cur + (uint32_t)r0 * 256u + (cb ^ x0v)) = f16x2(v0, v1);
                *(uint32_t*)(sm + OFF_ZN + cur + (uint32_t)r1 * 256u + (cb ^ x1v)) = f16x2(v2, v3);
            }
        }
        __syncthreads();                       // S3: xn visible; red reads done
        if (t < 128) red[t] = 0.f;             // re-arm stats for next tile

        // ===== pass z: out = (xn @ w_z^T + b_z) * gate =====
#pragma unroll
        for (int e = 0; e < 16; e++) accP[e] = 0.f;
        mm1(accP, azn, l16a, axv, W5, l16, xv);
        {
            float* o0 = out + (row0 + r0) * 128;
            float* o1 = out + (row0 + r1) * 128;
#pragma unroll
            for (int nb = 0; nb < 4; nb++) {
                int e = nb * 4, col = wc + nb * 8 + qt * 2;
                float2 bz = __half22float2(*(__half2*)(bh + 640 + col));
                float2 u, v2;
                u.x  = (accP[e]   + bz.x) * gate[e];
                u.y  = (accP[e+1] + bz.y) * gate[e+1];
                v2.x = (accP[e+2] + bz.x) * gate[e+2];
                v2.y = (accP[e+3] + bz.y) * gate[e+3];
                *(float2*)(o0 + col) = u;
                *(float2*)(o1 + col) = v2;
            }
        }

        // stage next tile's zn into the other buffer (overlaps pass-z tails)
        if (ntile < ntiles)
            ln_in_tile(sm, z, mask, ln_in_w, ln_in_b, (size_t)ntile * 64, nxtb,
                       mkh + ((it + 1) & 1) * 64, t);
        __syncthreads();                       // S_end: zn[nxt] ready; red zeroed
    }
}

extern "C" void kernel_launch(void* const* d_in, const int* in_sizes, int n_in,
                              void* d_out, int out_size) {
    const float* z        = (const float*)d_in[0];
    const float* mask     = (const float*)d_in[1];
    const float* w_ap     = (const float*)d_in[2];
    const float* b_ap     = (const float*)d_in[3];
    const float* w_bp     = (const float*)d_in[4];
    const float* b_bp     = (const float*)d_in[5];
    const float* w_ag     = (const float*)d_in[6];
    const float* b_ag     = (const float*)d_in[7];
    const float* w_bg     = (const float*)d_in[8];
    const float* b_bg     = (const float*)d_in[9];
    const float* w_g      = (const float*)d_in[10];
    const float* b_g      = (const float*)d_in[11];
    const float* w_z      = (const float*)d_in[12];
    const float* b_z      = (const float*)d_in[13];
    const float* ln_in_w  = (const float*)d_in[14];
    const float* ln_in_b  = (const float*)d_in[15];
    const float* ln_out_w = (const float*)d_in[16];
    const float* ln_out_b = (const float*)d_in[17];
    float* out = (float*)d_out;

    const int rows = in_sizes[1];      // B*N*N
    const int ntiles = rows / 64;      // 2304

    static int nsm = 0;
    if (!nsm) {
        cudaFuncSetAttribute(tmu_kernel, cudaFuncAttributeMaxDynamicSharedMemorySize, SMEM_BYTES);
        if (cudaDeviceGetAttribute(&nsm, cudaDevAttrMultiProcessorCount, 0) != cudaSuccess || nsm <= 0)
            nsm = 148;
    }
    int grid = nsm < ntiles ? nsm : ntiles;

    tmu_kernel<<<grid, NT, SMEM_BYTES>>>(z, mask,
                                         w_ap, b_ap, w_bp, b_bp,
                                         w_ag, b_ag, w_bg, b_bg,
                                         w_g, b_g, w_z, b_z,
                                         ln_in_w, ln_in_b, ln_out_w, ln_out_b,
                                         out, ntiles);
}